// round 15
// baseline (speedup 1.0000x reference)
#include <cuda_runtime.h>
#include <cuda_bf16.h>
#include <cstdint>

#define NN 100000
#define EE 1600000
#define F_IN 128
#define HID 64
#define NH 4
#define NC 16
#define D1 (NH*HID)   // 256
#define D2 (NH*NC)    // 64
#define MPAD 100032   // 1563 * 64

#define SBLKS 250
#define SCHUNK 400    // SBLKS*SCHUNK == NN

// ---------------- scratch ----------------
__device__ __align__(16) __nv_bfloat16 g_hb  [(size_t)MPAD * F_IN];
__device__ __align__(16) __nv_bfloat16 g_hagg[(size_t)MPAD * (NH * F_IN)];  // per-head aggregated h
__device__ __align__(16) __nv_bfloat16 g_h1b [(size_t)MPAD * D1];
__device__ __align__(16) __nv_bfloat16 g_Wh2b[(size_t)NN * D2];
__device__ __align__(16) float g_h2 [(size_t)NN * D2];
__device__ __align__(16) float g_s1d[NN * NH];
__device__ __align__(16) float g_s1s[NN * NH];
__device__ __align__(16) float g_s2d[NN * NH];
__device__ __align__(16) float g_s2s[NN * NH];
__device__ int   g_cnt[NN];
__device__ int   g_rowptr[NN + 1];
__device__ int   g_csr_src[EE];
__device__ int   g_bsum[SBLKS];
__device__ int   g_boff[SBLKS];
__device__ __align__(16) __nv_bfloat16 g_W1bt[D1 * F_IN];   // [h*64+o][k]
__device__ __align__(16) __nv_bfloat16 g_W2bt[D2 * D1];
__device__ __align__(16) float g_wa1d[NH * F_IN], g_wa1s[NH * F_IN];
__device__ __align__(16) float g_wa2d[NH * D1],  g_wa2s[NH * D1];
__device__ float g_bd1[NH], g_bs1[NH], g_bd2[NH], g_bs2[NH];
__device__ unsigned g_ms1[NH], g_ms2[NH];
__device__ float g_acc[NC];

__device__ __forceinline__ unsigned encf(float f) {
    unsigned u = __float_as_uint(f);
    return (u & 0x80000000u) ? ~u : (u | 0x80000000u);
}
__device__ __forceinline__ float decf(unsigned u) {
    return (u & 0x80000000u) ? __uint_as_float(u & 0x7fffffffu) : __uint_as_float(~u);
}

// ---------------- init + weight transpose (merged) ----------------
__global__ void prep_wb_k(const float* __restrict__ W1, const float* __restrict__ W2) {
    int i = blockIdx.x * blockDim.x + threadIdx.x;
    if (i < NN) g_cnt[i] = 0;
    if (i < NC) g_acc[i] = 0.f;
    if (i < NH) { g_ms1[i] = encf(-1e30f); g_ms2[i] = encf(-1e30f); }
    if (i < D1 * F_IN) {
        int n = i >> 7, k = i & 127;
        int h = n >> 6, o = n & 63;
        g_W1bt[i] = __float2bfloat16(W1[(h * F_IN + k) * HID + o]);
    }
    if (i < D2 * D1) {
        int n = i >> 8, k = i & 255;
        int h = n >> 4, c = n & 15;
        g_W2bt[i] = __float2bfloat16(W2[(h * D1 + k) * NC + c]);
    }
}

__global__ void prep_wa_k(const float* __restrict__ W1, const float* __restrict__ a1,
                          const float* __restrict__ b1, const float* __restrict__ ab1,
                          const float* __restrict__ W2, const float* __restrict__ a2,
                          const float* __restrict__ b2, const float* __restrict__ ab2) {
    int gw = (blockIdx.x * blockDim.x + threadIdx.x) >> 5;
    int lane = threadIdx.x & 31;
    if (gw < 1024) {
        int idx = gw & 511;
        int h = idx >> 7, k = idx & 127;
        const float* ap = a1 + h * 2 * HID + ((gw < 512) ? 0 : HID);
        float s = 0.f;
        for (int o = lane; o < HID; o += 32) s += W1[(h * F_IN + k) * HID + o] * ap[o];
#pragma unroll
        for (int off = 16; off; off >>= 1) s += __shfl_xor_sync(0xffffffffu, s, off);
        if (lane == 0) { if (gw < 512) g_wa1d[idx] = s; else g_wa1s[idx] = s; }
    } else if (gw < 3072) {
        int idx = (gw - 1024) & 1023;
        int h = idx >> 8, k = idx & 255;
        bool dpart = gw < 2048;
        const float* ap = a2 + h * 2 * NC + (dpart ? 0 : NC);
        float s = (lane < NC) ? W2[(h * D1 + k) * NC + lane] * ap[lane] : 0.f;
#pragma unroll
        for (int off = 16; off; off >>= 1) s += __shfl_xor_sync(0xffffffffu, s, off);
        if (lane == 0) { if (dpart) g_wa2d[idx] = s; else g_wa2s[idx] = s; }
    } else if (gw == 3072 && lane < NH) {
        int h = lane;
        float d1v = 0.f, s1v = 0.f, d2v = 0.f, s2v = 0.f;
        for (int o = 0; o < HID; o++) {
            d1v += b1[h * HID + o] * a1[h * 2 * HID + o];
            s1v += b1[h * HID + o] * a1[h * 2 * HID + HID + o];
        }
        for (int c = 0; c < NC; c++) {
            d2v += b2[h * NC + c] * a2[h * 2 * NC + c];
            s2v += b2[h * NC + c] * a2[h * 2 * NC + NC + c];
        }
        g_bd1[h] = d1v + ab1[h];  g_bs1[h] = s1v;
        g_bd2[h] = d2v + ab2[h];  g_bs2[h] = s2v;
    }
}

// ---------------- CSR build ----------------
__global__ void count_k(const int* __restrict__ dst) {
    int i = blockIdx.x * blockDim.x + threadIdx.x;
    if (i < EE) atomicAdd(&g_cnt[dst[i]], 1);
}

__device__ __forceinline__ int block_incl_scan(int v, int t, int* sh) {
    sh[t] = v;
    __syncthreads();
    for (int off = 1; off < 256; off <<= 1) {
        int x = (t >= off) ? sh[t - off] : 0;
        __syncthreads();
        sh[t] += x;
        __syncthreads();
    }
    return sh[t];
}

__global__ void scan1_k() {
    __shared__ int sh[256];
    int t = threadIdx.x, b = blockIdx.x;
    int base = b * SCHUNK;
    int s = 0;
#pragma unroll
    for (int u = 0; u < 2; u++) {
        int idx = t * 2 + u;
        if (idx < SCHUNK) s += g_cnt[base + idx];
    }
    int incl = block_incl_scan(s, t, sh);
    if (t == 255) g_bsum[b] = incl;
}

__global__ void scan2_k() {
    __shared__ int sh[256];
    int t = threadIdx.x;
    int v = (t < SBLKS) ? g_bsum[t] : 0;
    int incl = block_incl_scan(v, t, sh);
    if (t < SBLKS) g_boff[t] = incl - v;
    if (t == 0) g_rowptr[NN] = EE;
}

__global__ void scan3_k() {
    __shared__ int sh[256];
    int t = threadIdx.x, b = blockIdx.x;
    int base = b * SCHUNK;
    int c[2]; int s = 0;
#pragma unroll
    for (int u = 0; u < 2; u++) {
        int idx = t * 2 + u;
        c[u] = (idx < SCHUNK) ? g_cnt[base + idx] : 0;
        s += c[u];
    }
    int incl = block_incl_scan(s, t, sh);
    int run = g_boff[b] + incl - s;
#pragma unroll
    for (int u = 0; u < 2; u++) {
        int idx = t * 2 + u;
        if (idx < SCHUNK) {
            g_rowptr[base + idx] = run;
            g_cnt[base + idx] = run;
            run += c[u];
        }
    }
}

__global__ void scatter_k(const int* __restrict__ src, const int* __restrict__ dst) {
    int i = blockIdx.x * blockDim.x + threadIdx.x;
    if (i < EE) {
        int d = dst[i];
        int pos = atomicAdd(&g_cnt[d], 1);
        if ((unsigned)pos < EE) g_csr_src[pos] = src[i];
    }
}

__device__ __forceinline__ void row_bounds(int n, int& beg, int& end) {
    beg = g_rowptr[n];
    end = g_rowptr[n + 1];
    if (beg < 0 || end < beg || end > EE) { beg = 0; end = 0; }
    if (end - beg > 2048) end = beg + 2048;
}

// ---------------- bf16 tensor-core mma primitive ----------------
__device__ __forceinline__ void mma_bf16(float* c, const uint32_t* a, const uint32_t* b) {
    asm volatile(
        "mma.sync.aligned.m16n8k16.row.col.f32.bf16.bf16.f32 "
        "{%0,%1,%2,%3}, {%4,%5,%6,%7}, {%8,%9}, {%0,%1,%2,%3};\n"
        : "+f"(c[0]), "+f"(c[1]), "+f"(c[2]), "+f"(c[3])
        : "r"(a[0]), "r"(a[1]), "r"(a[2]), "r"(a[3]), "r"(b[0]), "r"(b[1]));
}

// ---------------- fused h->bf16 conversion + layer1 scores ----------------
__global__ __launch_bounds__(256) void conv_score1_k(const float* __restrict__ h) {
    __shared__ float swd[NH * F_IN], sws[NH * F_IN];
    int tid = threadIdx.x;
    for (int i = tid; i < NH * F_IN; i += 256) { swd[i] = g_wa1d[i]; sws[i] = g_wa1s[i]; }
    __syncthreads();
    int n = blockIdx.x * 8 + (tid >> 5);
    int lane = tid & 31;
    if (n >= MPAD) return;
    if (n >= NN) {
        *(uint2*)(g_hb + (size_t)n * F_IN + lane * 4) = make_uint2(0, 0);
        return;
    }
    float4 hv = *(const float4*)(h + (size_t)n * F_IN + lane * 4);
    __nv_bfloat162 c0 = __floats2bfloat162_rn(hv.x, hv.y);
    __nv_bfloat162 c1 = __floats2bfloat162_rn(hv.z, hv.w);
    uint2 pk;
    pk.x = *(uint32_t*)&c0; pk.y = *(uint32_t*)&c1;
    *(uint2*)(g_hb + (size_t)n * F_IN + lane * 4) = pk;

    float pd[4], ps[4];
#pragma unroll
    for (int v = 0; v < 4; v++) {
        int base = v * F_IN + lane * 4;
        pd[v] = hv.x * swd[base] + hv.y * swd[base + 1] + hv.z * swd[base + 2] + hv.w * swd[base + 3];
        ps[v] = hv.x * sws[base] + hv.y * sws[base + 1] + hv.z * sws[base + 2] + hv.w * sws[base + 3];
    }
#pragma unroll
    for (int off = 16; off; off >>= 1) {
#pragma unroll
        for (int v = 0; v < 4; v++) {
            pd[v] += __shfl_xor_sync(0xffffffffu, pd[v], off);
            ps[v] += __shfl_xor_sync(0xffffffffu, ps[v], off);
        }
    }
    if (lane == 0) {
#pragma unroll
        for (int v = 0; v < 4; v++) {
            g_s1d[n * NH + v] = pd[v] + g_bd1[v];
            g_s1s[n * NH + v] = ps[v] + g_bs1[v];
        }
    }
}

// ---------------- per-head global max of ss ----------------
template<int LAYER>
__global__ void maxss_k() {
    const float* __restrict__ s = (LAYER == 1) ? g_s1s : g_s2s;
    unsigned* __restrict__ ms = (LAYER == 1) ? g_ms1 : g_ms2;
    __shared__ float sh[8][4];
    int tid = threadIdx.x, lane = tid & 31, w = tid >> 5;
    float m[4] = {-1e30f, -1e30f, -1e30f, -1e30f};
    for (int i = blockIdx.x * 256 + tid; i < NN; i += gridDim.x * 256) {
        float4 v = ((const float4*)s)[i];
        m[0] = fmaxf(m[0], v.x); m[1] = fmaxf(m[1], v.y);
        m[2] = fmaxf(m[2], v.z); m[3] = fmaxf(m[3], v.w);
    }
#pragma unroll
    for (int off = 16; off; off >>= 1)
#pragma unroll
        for (int h = 0; h < 4; h++) m[h] = fmaxf(m[h], __shfl_xor_sync(0xffffffffu, m[h], off));
    if (lane == 0) { sh[w][0] = m[0]; sh[w][1] = m[1]; sh[w][2] = m[2]; sh[w][3] = m[3]; }
    __syncthreads();
    if (tid < 4) {
        float mm = sh[0][tid];
#pragma unroll
        for (int q = 1; q < 8; q++) mm = fmaxf(mm, sh[q][tid]);
        atomicMax(&ms[tid], encf(mm));
    }
}

// ---------------- layer1 aggregation on RAW h (256B/edge), all 4 heads ----------------
__global__ __launch_bounds__(256) void agg1h_k() {
    int n = blockIdx.x * 8 + (threadIdx.x >> 5);
    int lane = threadIdx.x & 31;
    if (n >= NN) return;
    int beg, end;
    row_bounds(n, beg, end);
    __nv_bfloat16* outp = g_hagg + (size_t)n * (NH * F_IN);
    if (end <= beg) {
#pragma unroll
        for (int h = 0; h < 4; h++)
            *(uint2*)(outp + h * F_IN + lane * 4) = make_uint2(0, 0);
        return;
    }
    float4 sd4 = ((const float4*)g_s1d)[n];
    float sdh[4] = {sd4.x, sd4.y, sd4.z, sd4.w};
    int myh = lane >> 3;
    float myb = sdh[myh];
    float ebh;
    {
        float eb = myb + decf(g_ms1[myh]);
        ebh = eb > 0.f ? eb : 0.2f * eb;
    }
    float o[4][4] = {};
    float sumown = 0.f;
    int base7 = lane & 7;
#pragma unroll 2
    for (int j = beg; j < end; j++) {
        int v = g_csr_src[j];
        int si = ((unsigned)v < NN) ? v : 0;
        float4 sv = ((const float4*)g_s1s)[si];
        float svh = (myh == 0) ? sv.x : (myh == 1) ? sv.y : (myh == 2) ? sv.z : sv.w;
        float e = myb + svh;
        e = e > 0.f ? e : 0.2f * e;
        float wown = __expf(e - ebh);
        sumown += wown;
        float w[4];
#pragma unroll
        for (int h = 0; h < 4; h++) w[h] = __shfl_sync(0xffffffffu, wown, h * 8 + base7);
        uint2 rv = *(const uint2*)(g_hb + (size_t)si * F_IN + lane * 4);
        __nv_bfloat162 p0, p1;
        p0 = *(__nv_bfloat162*)&rv.x;
        p1 = *(__nv_bfloat162*)&rv.y;
        float2 f01 = __bfloat1622float2(p0);
        float2 f23 = __bfloat1622float2(p1);
#pragma unroll
        for (int h = 0; h < 4; h++) {
            o[h][0] += w[h] * f01.x; o[h][1] += w[h] * f01.y;
            o[h][2] += w[h] * f23.x; o[h][3] += w[h] * f23.y;
        }
    }
#pragma unroll
    for (int h = 0; h < 4; h++) {
        float s = __shfl_sync(0xffffffffu, sumown, h * 8);
        float inv = 1.f / s;
        __nv_bfloat162 q0 = __floats2bfloat162_rn(o[h][0] * inv, o[h][1] * inv);
        __nv_bfloat162 q1 = __floats2bfloat162_rn(o[h][2] * inv, o[h][3] * inv);
        uint2 ov;
        ov.x = *(uint32_t*)&q0; ov.y = *(uint32_t*)&q1;
        *(uint2*)(outp + h * F_IN + lane * 4) = ov;
    }
}

// ---------------- layer1 GEMM on aggregated h: h1 = ELU(hagg_h @ W1_h + b1_h), per head ----------------
__global__ __launch_bounds__(256) void mma1h_k(const float* __restrict__ bias) {
    constexpr int LDA = 128 + 8;
    int hh = blockIdx.y;
    const __nv_bfloat16* __restrict__ A = g_hagg;             // lda = 512, col offset hh*128
    const __nv_bfloat16* __restrict__ B = g_W1bt + hh * 64 * F_IN;   // 64 rows x 128
    __shared__ __align__(16) __nv_bfloat16 sA[64 * LDA];
    __shared__ __align__(16) __nv_bfloat16 sB[64 * LDA];

    int tid = threadIdx.x, lane = tid & 31, w = tid >> 5;
    int g = lane >> 2, tig = lane & 3;
    int wm = w & 1, wn = w >> 1;
    int m0 = blockIdx.x * 64;

    float acc[2][2][4];
#pragma unroll
    for (int mi = 0; mi < 2; mi++)
#pragma unroll
        for (int ni = 0; ni < 2; ni++)
#pragma unroll
            for (int q = 0; q < 4; q++) acc[mi][ni][q] = 0.f;

    for (int u = tid; u < 64 * 16; u += 256) {
        int row = u >> 4, c8 = (u & 15) * 8;
        uint4 va = *(const uint4*)(A + (size_t)(m0 + row) * (NH * F_IN) + hh * F_IN + c8);
        uint32_t* d = (uint32_t*)(sA + row * LDA + c8);
        const uint32_t* s = (const uint32_t*)&va;
        d[0] = s[0]; d[1] = s[1]; d[2] = s[2]; d[3] = s[3];
        uint4 vb = *(const uint4*)(B + row * F_IN + c8);
        d = (uint32_t*)(sB + row * LDA + c8);
        s = (const uint32_t*)&vb;
        d[0] = s[0]; d[1] = s[1]; d[2] = s[2]; d[3] = s[3];
    }
    __syncthreads();
#pragma unroll
    for (int ks = 0; ks < 8; ks++) {
        int k0 = ks * 16 + 2 * tig;
        uint32_t a[2][4], b[2][2];
#pragma unroll
        for (int mi = 0; mi < 2; mi++) {
            int r0 = wm * 32 + mi * 16 + g;
            a[mi][0] = *(const uint32_t*)(sA + r0 * LDA + k0);
            a[mi][1] = *(const uint32_t*)(sA + (r0 + 8) * LDA + k0);
            a[mi][2] = *(const uint32_t*)(sA + r0 * LDA + k0 + 8);
            a[mi][3] = *(const uint32_t*)(sA + (r0 + 8) * LDA + k0 + 8);
        }
#pragma unroll
        for (int ni = 0; ni < 2; ni++) {
            int n = wn * 16 + ni * 8 + g;
            b[ni][0] = *(const uint32_t*)(sB + n * LDA + k0);
            b[ni][1] = *(const uint32_t*)(sB + n * LDA + k0 + 8);
        }
#pragma unroll
        for (int mi = 0; mi < 2; mi++)
#pragma unroll
            for (int ni = 0; ni < 2; ni++) mma_bf16(acc[mi][ni], a[mi], b[ni]);
    }
#pragma unroll
    for (int mi = 0; mi < 2; mi++) {
#pragma unroll
        for (int ni = 0; ni < 2; ni++) {
            int r = m0 + wm * 32 + mi * 16 + g;
            int n = wn * 16 + ni * 8 + 2 * tig;
            float bx = bias[hh * 64 + n], by = bias[hh * 64 + n + 1];
#pragma unroll
            for (int half = 0; half < 2; half++) {
                int rr = r + half * 8;
                if (rr < NN) {
                    bool empty = (g_rowptr[rr] >= g_rowptr[rr + 1]);
                    float v0 = empty ? 0.f : acc[mi][ni][2 * half]     + bx;
                    float v1 = empty ? 0.f : acc[mi][ni][2 * half + 1] + by;
                    v0 = v0 > 0.f ? v0 : (__expf(v0) - 1.f);   // ELU
                    v1 = v1 > 0.f ? v1 : (__expf(v1) - 1.f);
                    *(__nv_bfloat162*)(g_h1b + (size_t)rr * D1 + hh * 64 + n) =
                        __floats2bfloat162_rn(v0, v1);
                }
            }
        }
    }
}

// ---------------- layer2 GEMM (unchanged): Wh2 = h1 @ W2cat + b2 ----------------
__global__ __launch_bounds__(256) void mma2_k(const float* __restrict__ bias) {
    constexpr int K  = D1;
    constexpr int NT = D2;
    constexpr int KC = 128;
    constexpr int LDA = KC + 8;
    const __nv_bfloat16* __restrict__ A = g_h1b;
    const __nv_bfloat16* __restrict__ B = g_W2bt;
    __nv_bfloat16* __restrict__ C       = g_Wh2b;

    __shared__ __align__(16) __nv_bfloat16 sA[64 * LDA];
    __shared__ __align__(16) __nv_bfloat16 sB[64 * LDA];

    int tid = threadIdx.x, lane = tid & 31, w = tid >> 5;
    int g = lane >> 2, tig = lane & 3;
    int wm = w & 1, wn = w >> 1;
    int m0 = blockIdx.x * 64, n0 = blockIdx.y * 64;

    float acc[2][2][4];
#pragma unroll
    for (int mi = 0; mi < 2; mi++)
#pragma unroll
        for (int ni = 0; ni < 2; ni++)
#pragma unroll
            for (int q = 0; q < 4; q++) acc[mi][ni][q] = 0.f;

    for (int kc = 0; kc < K; kc += KC) {
        if (kc) __syncthreads();
        for (int u = tid; u < 64 * 16; u += 256) {
            int row = u >> 4, c8 = (u & 15) * 8;
            uint4 va = *(const uint4*)(A + (size_t)(m0 + row) * K + kc + c8);
            uint32_t* d = (uint32_t*)(sA + row * LDA + c8);
            const uint32_t* s = (const uint32_t*)&va;
            d[0] = s[0]; d[1] = s[1]; d[2] = s[2]; d[3] = s[3];
            uint4 vb = *(const uint4*)(B + (size_t)(n0 + row) * K + kc + c8);
            d = (uint32_t*)(sB + row * LDA + c8);
            s = (const uint32_t*)&vb;
            d[0] = s[0]; d[1] = s[1]; d[2] = s[2]; d[3] = s[3];
        }
        __syncthreads();
#pragma unroll
        for (int ks = 0; ks < KC / 16; ks++) {
            int k0 = ks * 16 + 2 * tig;
            uint32_t a[2][4], b[2][2];
#pragma unroll
            for (int mi = 0; mi < 2; mi++) {
                int r0 = wm * 32 + mi * 16 + g;
                a[mi][0] = *(const uint32_t*)(sA + r0 * LDA + k0);
                a[mi][1] = *(const uint32_t*)(sA + (r0 + 8) * LDA + k0);
                a[mi][2] = *(const uint32_t*)(sA + r0 * LDA + k0 + 8);
                a[mi][3] = *(const uint32_t*)(sA + (r0 + 8) * LDA + k0 + 8);
            }
#pragma unroll
            for (int ni = 0; ni < 2; ni++) {
                int n = wn * 16 + ni * 8 + g;
                b[ni][0] = *(const uint32_t*)(sB + n * LDA + k0);
                b[ni][1] = *(const uint32_t*)(sB + n * LDA + k0 + 8);
            }
#pragma unroll
            for (int mi = 0; mi < 2; mi++)
#pragma unroll
                for (int ni = 0; ni < 2; ni++) mma_bf16(acc[mi][ni], a[mi], b[ni]);
        }
    }
#pragma unroll
    for (int mi = 0; mi < 2; mi++) {
#pragma unroll
        for (int ni = 0; ni < 2; ni++) {
            int r = m0 + wm * 32 + mi * 16 + g;
            int n = n0 + wn * 16 + ni * 8 + 2 * tig;
            float bx = bias[n], by = bias[n + 1];
            if (r < NN)
                *(__nv_bfloat162*)(C + (size_t)r * NT + n) =
                    __floats2bfloat162_rn(acc[mi][ni][0] + bx, acc[mi][ni][1] + by);
            if (r + 8 < NN)
                *(__nv_bfloat162*)(C + (size_t)(r + 8) * NT + n) =
                    __floats2bfloat162_rn(acc[mi][ni][2] + bx, acc[mi][ni][3] + by);
        }
    }
}

// ---------------- layer2 scores ----------------
__global__ __launch_bounds__(256) void score2_k() {
    __shared__ float swd[NH * D1], sws[NH * D1];
    int tid = threadIdx.x;
    for (int i = tid; i < NH * D1; i += 256) { swd[i] = g_wa2d[i]; sws[i] = g_wa2s[i]; }
    __syncthreads();
    int n = blockIdx.x * 8 + (tid >> 5);
    int lane = tid & 31;
    if (n >= NN) return;
    uint4 v = *(const uint4*)(g_h1b + (size_t)n * D1 + lane * 8);
    const __nv_bfloat162* p = (const __nv_bfloat162*)&v;
    float f[8];
#pragma unroll
    for (int j = 0; j < 4; j++) {
        float2 t2 = __bfloat1622float2(p[j]);
        f[2 * j] = t2.x; f[2 * j + 1] = t2.y;
    }
    float pd[4], ps[4];
#pragma unroll
    for (int vv = 0; vv < 4; vv++) {
        int base = vv * D1 + lane * 8;
        float sd = 0.f, ss = 0.f;
#pragma unroll
        for (int j = 0; j < 8; j++) { sd += f[j] * swd[base + j]; ss += f[j] * sws[base + j]; }
        pd[vv] = sd; ps[vv] = ss;
    }
#pragma unroll
    for (int off = 16; off; off >>= 1) {
#pragma unroll
        for (int vv = 0; vv < 4; vv++) {
            pd[vv] += __shfl_xor_sync(0xffffffffu, pd[vv], off);
            ps[vv] += __shfl_xor_sync(0xffffffffu, ps[vv], off);
        }
    }
    if (lane == 0) {
#pragma unroll
        for (int vv = 0; vv < 4; vv++) {
            g_s2d[n * NH + vv] = pd[vv] + g_bd2[vv];
            g_s2s[n * NH + vv] = ps[vv] + g_bs2[vv];
        }
    }
}

// ---------------- layer2 aggregation (gather Wh2, 128B/edge) ----------------
__global__ __launch_bounds__(256) void agg2_k() {
    int n = blockIdx.x * (blockDim.x >> 5) + (threadIdx.x >> 5);
    int lane = threadIdx.x & 31;
    if (n >= NN) return;
    int beg, end;
    row_bounds(n, beg, end);
    float2* outp = (float2*)(g_h2 + (size_t)n * D2);
    if (end <= beg) {
        outp[lane] = make_float2(0.f, 0.f);
        return;
    }
    int myh = lane >> 3;
    float sdh = g_s2d[n * NH + myh];
    float eb = sdh + decf(g_ms2[myh]);
    eb = eb > 0.f ? eb : 0.2f * eb;
    float sum = 0.f, o0 = 0.f, o1 = 0.f;
#pragma unroll 2
    for (int j = beg; j < end; j++) {
        int v = g_csr_src[j];
        int si = ((unsigned)v < NN) ? v : 0;
        float e = sdh + g_s2s[si * NH + myh];
        e = e > 0.f ? e : 0.2f * e;
        float w = __expf(e - eb);
        sum += w;
        __nv_bfloat162 rv = ((const __nv_bfloat162*)(g_Wh2b + (size_t)si * D2))[lane];
        float2 fr = __bfloat1622float2(rv);
        o0 += w * fr.x; o1 += w * fr.y;
    }
    float inv = 1.f / sum;
    outp[lane] = make_float2(o0 * inv, o1 * inv);
}

// ---------------- readout ----------------
__global__ void reduce_k() {
    __shared__ float s[NC];
    int t = threadIdx.x;
    if (t < NC) s[t] = 0.f;
    __syncthreads();
    int n = blockIdx.x * blockDim.x + t;
    if (n < NN) {
        const float* r = g_h2 + (size_t)n * D2;
        float z[NC];
        float mx = -1e30f;
#pragma unroll
        for (int c = 0; c < NC; c++) {
            z[c] = 0.25f * (r[c] + r[NC + c] + r[2 * NC + c] + r[3 * NC + c]);
            mx = fmaxf(mx, z[c]);
        }
        float sum = 0.f;
#pragma unroll
        for (int c = 0; c < NC; c++) { z[c] = __expf(z[c] - mx); sum += z[c]; }
        float inv = 1.f / sum;
#pragma unroll
        for (int c = 0; c < NC; c++) atomicAdd(&s[c], z[c] * inv);
    }
    __syncthreads();
    if (t < NC) atomicAdd(&g_acc[t], s[t]);
}

__global__ void final_k(const float* __restrict__ fc_w, const float* __restrict__ fc_b,
                        float* __restrict__ out) {
    __shared__ float hg[NC];
    int t = threadIdx.x;
    if (t < NC) hg[t] = g_acc[t] * (1.0f / (float)NN);
    __syncthreads();
    if (t < NC) {
        float s = fc_b[t];
#pragma unroll
        for (int j = 0; j < NC; j++) s += hg[j] * fc_w[t * NC + j];
        out[t] = s;
    }
}

// ---------------- launch ----------------
extern "C" void kernel_launch(void* const* d_in, const int* in_sizes, int n_in,
                              void* d_out, int out_size) {
    const float* h    = (const float*)d_in[0];
    const int*   src  = (const int*)d_in[1];
    const int*   dst  = (const int*)d_in[2];
    const float* W1   = (const float*)d_in[3];
    const float* b1   = (const float*)d_in[4];
    const float* a1   = (const float*)d_in[5];
    const float* ab1  = (const float*)d_in[6];
    const float* W2   = (const float*)d_in[7];
    const float* b2   = (const float*)d_in[8];
    const float* a2   = (const float*)d_in[9];
    const float* ab2  = (const float*)d_in[10];
    const float* fc_w = (const float*)d_in[11];
    const float* fc_b = (const float*)d_in[12];
    float* out = (float*)d_out;

    prep_wb_k<<<(NN + 255) / 256, 256>>>(W1, W2);   // also zeroes cnt/acc/ms
    prep_wa_k<<<(3073 * 32 + 255) / 256, 256>>>(W1, a1, b1, ab1, W2, a2, b2, ab2);

    count_k<<<(EE + 255) / 256, 256>>>(dst);
    scan1_k<<<SBLKS, 256>>>();
    scan2_k<<<1, 256>>>();
    scan3_k<<<SBLKS, 256>>>();
    scatter_k<<<(EE + 255) / 256, 256>>>(src, dst);

    conv_score1_k<<<(MPAD + 7) / 8, 256>>>(h);
    maxss_k<1><<<64, 256>>>();

    // layer 1: aggregate raw h per head, then project (+ELU) on tensor cores
    agg1h_k<<<(NN + 7) / 8, 256>>>();
    {
        dim3 grid(MPAD / 64, NH);
        mma1h_k<<<grid, 256>>>(b1);
    }

    // layer 2: project then aggregate
    {
        dim3 grid(MPAD / 64, D2 / 64);
        mma2_k<<<grid, 256>>>(b2);
    }
    score2_k<<<(NN + 7) / 8, 256>>>();
    maxss_k<2><<<64, 256>>>();
    agg2_k<<<(NN + 7) / 8, 256>>>();

    // readout
    reduce_k<<<(NN + 255) / 256, 256>>>();
    final_k<<<1, 32>>>(fc_w, fc_b, out);
}

// round 16
// speedup vs baseline: 1.9550x; 1.9550x over previous
#include <cuda_runtime.h>
#include <cuda_bf16.h>
#include <cstdint>

#define NN 100000
#define EE 1600000
#define F_IN 128
#define HID 64
#define NH 4
#define NC 16
#define D1 (NH*HID)   // 256
#define D2 (NH*NC)    // 64
#define MPAD 100032   // 1563 * 64

#define SBLKS 250
#define SCHUNK 400    // SBLKS*SCHUNK == NN

// ---------------- scratch ----------------
__device__ __align__(16) __nv_bfloat16 g_hb  [(size_t)MPAD * F_IN];
__device__ __align__(16) __nv_bfloat16 g_Wh1b[(size_t)NN * D1];
__device__ __align__(16) __nv_bfloat16 g_h1b [(size_t)MPAD * D1];
__device__ __align__(16) __nv_bfloat16 g_Wh2b[(size_t)NN * D2];
__device__ __align__(16) float g_h2 [(size_t)NN * D2];
__device__ __align__(16) float g_s1d[NN * NH];
__device__ __align__(16) float g_s1s[NN * NH];
__device__ __align__(16) float g_s2d[NN * NH];
__device__ __align__(16) float g_s2s[NN * NH];
__device__ int   g_cnt[NN];
__device__ int   g_rowptr[NN + 1];
__device__ int   g_csr_src[EE];
__device__ int   g_bsum[SBLKS];
__device__ int   g_boff[SBLKS];
__device__ __align__(16) __nv_bfloat16 g_W1bt[D1 * F_IN];
__device__ __align__(16) __nv_bfloat16 g_W2bt[D2 * D1];
__device__ __align__(16) float g_wa1d[NH * F_IN], g_wa1s[NH * F_IN];
__device__ __align__(16) float g_wa2d[NH * D1],  g_wa2s[NH * D1];
__device__ float g_bd1[NH], g_bs1[NH], g_bd2[NH], g_bs2[NH];
__device__ unsigned g_ms1[NH], g_ms2[NH];
__device__ float g_acc[NC];

__device__ __forceinline__ unsigned encf(float f) {
    unsigned u = __float_as_uint(f);
    return (u & 0x80000000u) ? ~u : (u | 0x80000000u);
}
__device__ __forceinline__ float decf(unsigned u) {
    return (u & 0x80000000u) ? __uint_as_float(u & 0x7fffffffu) : __uint_as_float(~u);
}

// ---------------- init ----------------
__global__ void zero_cnt_k() {
    int i = blockIdx.x * blockDim.x + threadIdx.x;
    if (i < NN) g_cnt[i] = 0;
}

__global__ void prep_wb_k(const float* __restrict__ W1, const float* __restrict__ W2) {
    int i = blockIdx.x * blockDim.x + threadIdx.x;
    if (i < NC) g_acc[i] = 0.f;
    if (i < NH) { g_ms1[i] = encf(-1e30f); g_ms2[i] = encf(-1e30f); }
    if (i < D1 * F_IN) {
        int n = i >> 7, k = i & 127;
        int h = n >> 6, o = n & 63;
        g_W1bt[i] = __float2bfloat16(W1[(h * F_IN + k) * HID + o]);
    }
    if (i < D2 * D1) {
        int n = i >> 8, k = i & 255;
        int h = n >> 4, c = n & 15;
        g_W2bt[i] = __float2bfloat16(W2[(h * D1 + k) * NC + c]);
    }
}

__global__ void prep_wa_k(const float* __restrict__ W1, const float* __restrict__ a1,
                          const float* __restrict__ b1, const float* __restrict__ ab1,
                          const float* __restrict__ W2, const float* __restrict__ a2,
                          const float* __restrict__ b2, const float* __restrict__ ab2) {
    int gw = (blockIdx.x * blockDim.x + threadIdx.x) >> 5;
    int lane = threadIdx.x & 31;
    if (gw < 1024) {
        int idx = gw & 511;
        int h = idx >> 7, k = idx & 127;
        const float* ap = a1 + h * 2 * HID + ((gw < 512) ? 0 : HID);
        float s = 0.f;
        for (int o = lane; o < HID; o += 32) s += W1[(h * F_IN + k) * HID + o] * ap[o];
#pragma unroll
        for (int off = 16; off; off >>= 1) s += __shfl_xor_sync(0xffffffffu, s, off);
        if (lane == 0) { if (gw < 512) g_wa1d[idx] = s; else g_wa1s[idx] = s; }
    } else if (gw < 3072) {
        int idx = (gw - 1024) & 1023;
        int h = idx >> 8, k = idx & 255;
        bool dpart = gw < 2048;
        const float* ap = a2 + h * 2 * NC + (dpart ? 0 : NC);
        float s = (lane < NC) ? W2[(h * D1 + k) * NC + lane] * ap[lane] : 0.f;
#pragma unroll
        for (int off = 16; off; off >>= 1) s += __shfl_xor_sync(0xffffffffu, s, off);
        if (lane == 0) { if (dpart) g_wa2d[idx] = s; else g_wa2s[idx] = s; }
    } else if (gw == 3072 && lane < NH) {
        int h = lane;
        float d1v = 0.f, s1v = 0.f, d2v = 0.f, s2v = 0.f;
        for (int o = 0; o < HID; o++) {
            d1v += b1[h * HID + o] * a1[h * 2 * HID + o];
            s1v += b1[h * HID + o] * a1[h * 2 * HID + HID + o];
        }
        for (int c = 0; c < NC; c++) {
            d2v += b2[h * NC + c] * a2[h * 2 * NC + c];
            s2v += b2[h * NC + c] * a2[h * 2 * NC + NC + c];
        }
        g_bd1[h] = d1v + ab1[h];  g_bs1[h] = s1v;
        g_bd2[h] = d2v + ab2[h];  g_bs2[h] = s2v;
    }
}

// ---------------- CSR build ----------------
__global__ void count_k(const int* __restrict__ dst) {
    int i = blockIdx.x * blockDim.x + threadIdx.x;
    if (i < EE) atomicAdd(&g_cnt[dst[i]], 1);
}

__device__ __forceinline__ int block_incl_scan(int v, int t, int* sh) {
    sh[t] = v;
    __syncthreads();
    for (int off = 1; off < 256; off <<= 1) {
        int x = (t >= off) ? sh[t - off] : 0;
        __syncthreads();
        sh[t] += x;
        __syncthreads();
    }
    return sh[t];
}

__global__ void scan1_k() {
    __shared__ int sh[256];
    int t = threadIdx.x, b = blockIdx.x;
    int base = b * SCHUNK;
    int s = 0;
#pragma unroll
    for (int u = 0; u < 2; u++) {
        int idx = t * 2 + u;
        if (idx < SCHUNK) s += g_cnt[base + idx];
    }
    int incl = block_incl_scan(s, t, sh);
    if (t == 255) g_bsum[b] = incl;
}

__global__ void scan2_k() {
    __shared__ int sh[256];
    int t = threadIdx.x;
    int v = (t < SBLKS) ? g_bsum[t] : 0;
    int incl = block_incl_scan(v, t, sh);
    if (t < SBLKS) g_boff[t] = incl - v;
    if (t == 0) g_rowptr[NN] = EE;
}

__global__ void scan3_k() {
    __shared__ int sh[256];
    int t = threadIdx.x, b = blockIdx.x;
    int base = b * SCHUNK;
    int c[2]; int s = 0;
#pragma unroll
    for (int u = 0; u < 2; u++) {
        int idx = t * 2 + u;
        c[u] = (idx < SCHUNK) ? g_cnt[base + idx] : 0;
        s += c[u];
    }
    int incl = block_incl_scan(s, t, sh);
    int run = g_boff[b] + incl - s;
#pragma unroll
    for (int u = 0; u < 2; u++) {
        int idx = t * 2 + u;
        if (idx < SCHUNK) {
            g_rowptr[base + idx] = run;
            g_cnt[base + idx] = run;
            run += c[u];
        }
    }
}

__global__ void scatter_k(const int* __restrict__ src, const int* __restrict__ dst) {
    int i = blockIdx.x * blockDim.x + threadIdx.x;
    if (i < EE) {
        int d = dst[i];
        int pos = atomicAdd(&g_cnt[d], 1);
        if ((unsigned)pos < EE) g_csr_src[pos] = src[i];
    }
}

__device__ __forceinline__ void row_bounds(int n, int& beg, int& end) {
    beg = g_rowptr[n];
    end = g_rowptr[n + 1];
    if (beg < 0 || end < beg || end > EE) { beg = 0; end = 0; }
    if (end - beg > 2048) end = beg + 2048;
}

// ---------------- bf16 tensor-core GEMM ----------------
__device__ __forceinline__ void mma_bf16(float* c, const uint32_t* a, const uint32_t* b) {
    asm volatile(
        "mma.sync.aligned.m16n8k16.row.col.f32.bf16.bf16.f32 "
        "{%0,%1,%2,%3}, {%4,%5,%6,%7}, {%8,%9}, {%0,%1,%2,%3};\n"
        : "+f"(c[0]), "+f"(c[1]), "+f"(c[2]), "+f"(c[3])
        : "r"(a[0]), "r"(a[1]), "r"(a[2]), "r"(a[3]), "r"(b[0]), "r"(b[1]));
}

template<int LAYER>
__global__ __launch_bounds__(256) void mma_k(const float* __restrict__ bias) {
    constexpr int K  = (LAYER == 1) ? F_IN : D1;
    constexpr int NT = (LAYER == 1) ? D1 : D2;
    constexpr int KC = 128;
    constexpr int LDA = KC + 8;
    const __nv_bfloat16* __restrict__ A = (LAYER == 1) ? g_hb : g_h1b;
    const __nv_bfloat16* __restrict__ B = (LAYER == 1) ? g_W1bt : g_W2bt;
    __nv_bfloat16* __restrict__ C       = (LAYER == 1) ? g_Wh1b : g_Wh2b;

    __shared__ __align__(16) __nv_bfloat16 sA[64 * LDA];
    __shared__ __align__(16) __nv_bfloat16 sB[64 * LDA];

    int tid = threadIdx.x, lane = tid & 31, w = tid >> 5;
    int g = lane >> 2, tig = lane & 3;
    int wm = w & 1, wn = w >> 1;
    int m0 = blockIdx.x * 64, n0 = blockIdx.y * 64;

    float acc[2][2][4];
#pragma unroll
    for (int mi = 0; mi < 2; mi++)
#pragma unroll
        for (int ni = 0; ni < 2; ni++)
#pragma unroll
            for (int q = 0; q < 4; q++) acc[mi][ni][q] = 0.f;

    for (int kc = 0; kc < K; kc += KC) {
        if (kc) __syncthreads();
        for (int u = tid; u < 64 * 16; u += 256) {
            int row = u >> 4, c8 = (u & 15) * 8;
            uint4 va = *(const uint4*)(A + (size_t)(m0 + row) * K + kc + c8);
            uint32_t* d = (uint32_t*)(sA + row * LDA + c8);
            const uint32_t* s = (const uint32_t*)&va;
            d[0] = s[0]; d[1] = s[1]; d[2] = s[2]; d[3] = s[3];
            uint4 vb = *(const uint4*)(B + (size_t)(n0 + row) * K + kc + c8);
            d = (uint32_t*)(sB + row * LDA + c8);
            s = (const uint32_t*)&vb;
            d[0] = s[0]; d[1] = s[1]; d[2] = s[2]; d[3] = s[3];
        }
        __syncthreads();
#pragma unroll
        for (int ks = 0; ks < KC / 16; ks++) {
            int k0 = ks * 16 + 2 * tig;
            uint32_t a[2][4], b[2][2];
#pragma unroll
            for (int mi = 0; mi < 2; mi++) {
                int r0 = wm * 32 + mi * 16 + g;
                a[mi][0] = *(const uint32_t*)(sA + r0 * LDA + k0);
                a[mi][1] = *(const uint32_t*)(sA + (r0 + 8) * LDA + k0);
                a[mi][2] = *(const uint32_t*)(sA + r0 * LDA + k0 + 8);
                a[mi][3] = *(const uint32_t*)(sA + (r0 + 8) * LDA + k0 + 8);
            }
#pragma unroll
            for (int ni = 0; ni < 2; ni++) {
                int n = wn * 16 + ni * 8 + g;
                b[ni][0] = *(const uint32_t*)(sB + n * LDA + k0);
                b[ni][1] = *(const uint32_t*)(sB + n * LDA + k0 + 8);
            }
#pragma unroll
            for (int mi = 0; mi < 2; mi++)
#pragma unroll
                for (int ni = 0; ni < 2; ni++) mma_bf16(acc[mi][ni], a[mi], b[ni]);
        }
    }
#pragma unroll
    for (int mi = 0; mi < 2; mi++) {
#pragma unroll
        for (int ni = 0; ni < 2; ni++) {
            int r = m0 + wm * 32 + mi * 16 + g;
            int n = n0 + wn * 16 + ni * 8 + 2 * tig;
            float bx = bias[n], by = bias[n + 1];
            if (r < NN)
                *(__nv_bfloat162*)(C + (size_t)r * NT + n) =
                    __floats2bfloat162_rn(acc[mi][ni][0] + bx, acc[mi][ni][1] + by);
            if (r + 8 < NN)
                *(__nv_bfloat162*)(C + (size_t)(r + 8) * NT + n) =
                    __floats2bfloat162_rn(acc[mi][ni][2] + bx, acc[mi][ni][3] + by);
        }
    }
}

// ---------------- fused h->bf16 conversion + layer1 scores ----------------
__global__ __launch_bounds__(256) void conv_score1_k(const float* __restrict__ h) {
    __shared__ float swd[NH * F_IN], sws[NH * F_IN];
    int tid = threadIdx.x;
    for (int i = tid; i < NH * F_IN; i += 256) { swd[i] = g_wa1d[i]; sws[i] = g_wa1s[i]; }
    __syncthreads();
    int n = blockIdx.x * 8 + (tid >> 5);
    int lane = tid & 31;
    if (n >= MPAD) return;
    if (n >= NN) {
        *(uint2*)(g_hb + (size_t)n * F_IN + lane * 4) = make_uint2(0, 0);
        return;
    }
    float4 hv = *(const float4*)(h + (size_t)n * F_IN + lane * 4);
    __nv_bfloat162 c0 = __floats2bfloat162_rn(hv.x, hv.y);
    __nv_bfloat162 c1 = __floats2bfloat162_rn(hv.z, hv.w);
    uint2 pk;
    pk.x = *(uint32_t*)&c0; pk.y = *(uint32_t*)&c1;
    *(uint2*)(g_hb + (size_t)n * F_IN + lane * 4) = pk;

    float pd[4], ps[4];
#pragma unroll
    for (int v = 0; v < 4; v++) {
        int base = v * F_IN + lane * 4;
        pd[v] = hv.x * swd[base] + hv.y * swd[base + 1] + hv.z * swd[base + 2] + hv.w * swd[base + 3];
        ps[v] = hv.x * sws[base] + hv.y * sws[base + 1] + hv.z * sws[base + 2] + hv.w * sws[base + 3];
    }
#pragma unroll
    for (int off = 16; off; off >>= 1) {
#pragma unroll
        for (int v = 0; v < 4; v++) {
            pd[v] += __shfl_xor_sync(0xffffffffu, pd[v], off);
            ps[v] += __shfl_xor_sync(0xffffffffu, ps[v], off);
        }
    }
    if (lane == 0) {
#pragma unroll
        for (int v = 0; v < 4; v++) {
            g_s1d[n * NH + v] = pd[v] + g_bd1[v];
            g_s1s[n * NH + v] = ps[v] + g_bs1[v];
        }
    }
}

__global__ __launch_bounds__(256) void score2_k() {
    __shared__ float swd[NH * D1], sws[NH * D1];
    int tid = threadIdx.x;
    for (int i = tid; i < NH * D1; i += 256) { swd[i] = g_wa2d[i]; sws[i] = g_wa2s[i]; }
    __syncthreads();
    int n = blockIdx.x * 8 + (tid >> 5);
    int lane = tid & 31;
    if (n >= NN) return;
    uint4 v = *(const uint4*)(g_h1b + (size_t)n * D1 + lane * 8);
    const __nv_bfloat162* p = (const __nv_bfloat162*)&v;
    float f[8];
#pragma unroll
    for (int j = 0; j < 4; j++) {
        float2 t2 = __bfloat1622float2(p[j]);
        f[2 * j] = t2.x; f[2 * j + 1] = t2.y;
    }
    float pd[4], ps[4];
#pragma unroll
    for (int vv = 0; vv < 4; vv++) {
        int base = vv * D1 + lane * 8;
        float sd = 0.f, ss = 0.f;
#pragma unroll
        for (int j = 0; j < 8; j++) { sd += f[j] * swd[base + j]; ss += f[j] * sws[base + j]; }
        pd[vv] = sd; ps[vv] = ss;
    }
#pragma unroll
    for (int off = 16; off; off >>= 1) {
#pragma unroll
        for (int vv = 0; vv < 4; vv++) {
            pd[vv] += __shfl_xor_sync(0xffffffffu, pd[vv], off);
            ps[vv] += __shfl_xor_sync(0xffffffffu, ps[vv], off);
        }
    }
    if (lane == 0) {
#pragma unroll
        for (int vv = 0; vv < 4; vv++) {
            g_s2d[n * NH + vv] = pd[vv] + g_bd2[vv];
            g_s2s[n * NH + vv] = ps[vv] + g_bs2[vv];
        }
    }
}

// ---------------- per-head global max of ss ----------------
template<int LAYER>
__global__ void maxss_k() {
    const float* __restrict__ s = (LAYER == 1) ? g_s1s : g_s2s;
    unsigned* __restrict__ ms = (LAYER == 1) ? g_ms1 : g_ms2;
    __shared__ float sh[8][4];
    int tid = threadIdx.x, lane = tid & 31, w = tid >> 5;
    float m[4] = {-1e30f, -1e30f, -1e30f, -1e30f};
    for (int i = blockIdx.x * 256 + tid; i < NN; i += gridDim.x * 256) {
        float4 v = ((const float4*)s)[i];
        m[0] = fmaxf(m[0], v.x); m[1] = fmaxf(m[1], v.y);
        m[2] = fmaxf(m[2], v.z); m[3] = fmaxf(m[3], v.w);
    }
#pragma unroll
    for (int off = 16; off; off >>= 1)
#pragma unroll
        for (int h = 0; h < 4; h++) m[h] = fmaxf(m[h], __shfl_xor_sync(0xffffffffu, m[h], off));
    if (lane == 0) { sh[w][0] = m[0]; sh[w][1] = m[1]; sh[w][2] = m[2]; sh[w][3] = m[3]; }
    __syncthreads();
    if (tid < 4) {
        float mm = sh[0][tid];
#pragma unroll
        for (int q = 1; q < 8; q++) mm = fmaxf(mm, sh[q][tid]);
        atomicMax(&ms[tid], encf(mm));
    }
}

// ---------------- single-pass aggregation (R14 proven version) ----------------
__global__ __launch_bounds__(256) void agg1_k() {
    int n = blockIdx.x * (blockDim.x >> 5) + (threadIdx.x >> 5);
    int lane = threadIdx.x & 31;
    if (n >= NN) return;
    int beg, end;
    row_bounds(n, beg, end);
    if (end <= beg) {
        *(uint4*)(g_h1b + (size_t)n * D1 + lane * 8) = make_uint4(0, 0, 0, 0);
        return;
    }
    int myh = lane >> 3;
    float sdh = g_s1d[n * NH + myh];
    float eb = sdh + decf(g_ms1[myh]);
    eb = eb > 0.f ? eb : 0.2f * eb;
    float sum = 0.f;
    float o[8] = {0.f, 0.f, 0.f, 0.f, 0.f, 0.f, 0.f, 0.f};

    int j = beg;
    for (; j + 4 <= end; j += 4) {
        int si[4];
#pragma unroll
        for (int q = 0; q < 4; q++) {
            int v = g_csr_src[j + q];
            si[q] = ((unsigned)v < NN) ? v : 0;
        }
        float ss[4];
#pragma unroll
        for (int q = 0; q < 4; q++) ss[q] = g_s1s[si[q] * NH + myh];
        uint4 rv[4];
#pragma unroll
        for (int q = 0; q < 4; q++) rv[q] = *(const uint4*)(g_Wh1b + (size_t)si[q] * D1 + lane * 8);
#pragma unroll
        for (int q = 0; q < 4; q++) {
            float e = sdh + ss[q];
            e = e > 0.f ? e : 0.2f * e;
            float w = __expf(e - eb);
            sum += w;
            const __nv_bfloat162* pp = (const __nv_bfloat162*)&rv[q];
#pragma unroll
            for (int p = 0; p < 4; p++) {
                float2 fq = __bfloat1622float2(pp[p]);
                o[2 * p]     += w * fq.x;
                o[2 * p + 1] += w * fq.y;
            }
        }
    }
    for (; j < end; j++) {
        int v = g_csr_src[j];
        int si = ((unsigned)v < NN) ? v : 0;
        float e = sdh + g_s1s[si * NH + myh];
        e = e > 0.f ? e : 0.2f * e;
        float w = __expf(e - eb);
        sum += w;
        uint4 rv = *(const uint4*)(g_Wh1b + (size_t)si * D1 + lane * 8);
        const __nv_bfloat162* pp = (const __nv_bfloat162*)&rv;
#pragma unroll
        for (int p = 0; p < 4; p++) {
            float2 fq = __bfloat1622float2(pp[p]);
            o[2 * p]     += w * fq.x;
            o[2 * p + 1] += w * fq.y;
        }
    }
    float inv = 1.f / sum;
    uint4 ov;
    __nv_bfloat162* op = (__nv_bfloat162*)&ov;
#pragma unroll
    for (int q = 0; q < 4; q++) {
        float v0 = o[2 * q] * inv,  v1 = o[2 * q + 1] * inv;
        v0 = v0 > 0.f ? v0 : (__expf(v0) - 1.f);
        v1 = v1 > 0.f ? v1 : (__expf(v1) - 1.f);
        op[q] = __floats2bfloat162_rn(v0, v1);
    }
    *(uint4*)(g_h1b + (size_t)n * D1 + lane * 8) = ov;
}

__global__ __launch_bounds__(256) void agg2_k() {
    int n = blockIdx.x * (blockDim.x >> 5) + (threadIdx.x >> 5);
    int lane = threadIdx.x & 31;
    if (n >= NN) return;
    int beg, end;
    row_bounds(n, beg, end);
    float2* outp = (float2*)(g_h2 + (size_t)n * D2);
    if (end <= beg) {
        outp[lane] = make_float2(0.f, 0.f);
        return;
    }
    int myh = lane >> 3;
    float sdh = g_s2d[n * NH + myh];
    float eb = sdh + decf(g_ms2[myh]);
    eb = eb > 0.f ? eb : 0.2f * eb;
    float sum = 0.f, o0 = 0.f, o1 = 0.f;

    int j = beg;
    for (; j + 4 <= end; j += 4) {
        int si[4];
#pragma unroll
        for (int q = 0; q < 4; q++) {
            int v = g_csr_src[j + q];
            si[q] = ((unsigned)v < NN) ? v : 0;
        }
        float ss[4];
#pragma unroll
        for (int q = 0; q < 4; q++) ss[q] = g_s2s[si[q] * NH + myh];
        __nv_bfloat162 rv[4];
#pragma unroll
        for (int q = 0; q < 4; q++) rv[q] = ((const __nv_bfloat162*)(g_Wh2b + (size_t)si[q] * D2))[lane];
#pragma unroll
        for (int q = 0; q < 4; q++) {
            float e = sdh + ss[q];
            e = e > 0.f ? e : 0.2f * e;
            float w = __expf(e - eb);
            sum += w;
            float2 fr = __bfloat1622float2(rv[q]);
            o0 += w * fr.x; o1 += w * fr.y;
        }
    }
    for (; j < end; j++) {
        int v = g_csr_src[j];
        int si = ((unsigned)v < NN) ? v : 0;
        float e = sdh + g_s2s[si * NH + myh];
        e = e > 0.f ? e : 0.2f * e;
        float w = __expf(e - eb);
        sum += w;
        __nv_bfloat162 rv = ((const __nv_bfloat162*)(g_Wh2b + (size_t)si * D2))[lane];
        float2 fr = __bfloat1622float2(rv);
        o0 += w * fr.x; o1 += w * fr.y;
    }
    float inv = 1.f / sum;
    outp[lane] = make_float2(o0 * inv, o1 * inv);
}

// ---------------- readout ----------------
__global__ void reduce_k() {
    __shared__ float s[NC];
    int t = threadIdx.x;
    if (t < NC) s[t] = 0.f;
    __syncthreads();
    int n = blockIdx.x * blockDim.x + t;
    if (n < NN) {
        const float* r = g_h2 + (size_t)n * D2;
        float z[NC];
        float mx = -1e30f;
#pragma unroll
        for (int c = 0; c < NC; c++) {
            z[c] = 0.25f * (r[c] + r[NC + c] + r[2 * NC + c] + r[3 * NC + c]);
            mx = fmaxf(mx, z[c]);
        }
        float sum = 0.f;
#pragma unroll
        for (int c = 0; c < NC; c++) { z[c] = __expf(z[c] - mx); sum += z[c]; }
        float inv = 1.f / sum;
#pragma unroll
        for (int c = 0; c < NC; c++) atomicAdd(&s[c], z[c] * inv);
    }
    __syncthreads();
    if (t < NC) atomicAdd(&g_acc[t], s[t]);
}

__global__ void final_k(const float* __restrict__ fc_w, const float* __restrict__ fc_b,
                        float* __restrict__ out) {
    __shared__ float hg[NC];
    int t = threadIdx.x;
    if (t < NC) hg[t] = g_acc[t] * (1.0f / (float)NN);
    __syncthreads();
    if (t < NC) {
        float s = fc_b[t];
#pragma unroll
        for (int j = 0; j < NC; j++) s += hg[j] * fc_w[t * NC + j];
        out[t] = s;
    }
}

// ---------------- launch (fork-join streams inside the graph) ----------------
extern "C" void kernel_launch(void* const* d_in, const int* in_sizes, int n_in,
                              void* d_out, int out_size) {
    const float* h    = (const float*)d_in[0];
    const int*   src  = (const int*)d_in[1];
    const int*   dst  = (const int*)d_in[2];
    const float* W1   = (const float*)d_in[3];
    const float* b1   = (const float*)d_in[4];
    const float* a1   = (const float*)d_in[5];
    const float* ab1  = (const float*)d_in[6];
    const float* W2   = (const float*)d_in[7];
    const float* b2   = (const float*)d_in[8];
    const float* a2   = (const float*)d_in[9];
    const float* ab2  = (const float*)d_in[10];
    const float* fc_w = (const float*)d_in[11];
    const float* fc_b = (const float*)d_in[12];
    float* out = (float*)d_out;

    static cudaStream_t sCSR = nullptr, sB = nullptr, sC = nullptr;
    static cudaEvent_t ev0 = nullptr, evCSR = nullptr, evB = nullptr, ev1 = nullptr, ev2 = nullptr;
    static bool ok = false;
    if (!sCSR) {
        bool good = true;
        good &= (cudaStreamCreateWithFlags(&sCSR, cudaStreamNonBlocking) == cudaSuccess);
        good &= (cudaStreamCreateWithFlags(&sB,   cudaStreamNonBlocking) == cudaSuccess);
        good &= (cudaStreamCreateWithFlags(&sC,   cudaStreamNonBlocking) == cudaSuccess);
        good &= (cudaEventCreateWithFlags(&ev0,   cudaEventDisableTiming) == cudaSuccess);
        good &= (cudaEventCreateWithFlags(&evCSR, cudaEventDisableTiming) == cudaSuccess);
        good &= (cudaEventCreateWithFlags(&evB,   cudaEventDisableTiming) == cudaSuccess);
        good &= (cudaEventCreateWithFlags(&ev1,   cudaEventDisableTiming) == cudaSuccess);
        good &= (cudaEventCreateWithFlags(&ev2,   cudaEventDisableTiming) == cudaSuccess);
        ok = good;
    }

    if (ok) {
        // fork from the capture (default) stream
        cudaEventRecord(ev0, 0);
        cudaStreamWaitEvent(sCSR, ev0, 0);
        cudaStreamWaitEvent(sB, ev0, 0);

        // stream A: CSR build
        zero_cnt_k<<<(NN + 255) / 256, 256, 0, sCSR>>>();
        count_k<<<(EE + 255) / 256, 256, 0, sCSR>>>(dst);
        scan1_k<<<SBLKS, 256, 0, sCSR>>>();
        scan2_k<<<1, 256, 0, sCSR>>>();
        scan3_k<<<SBLKS, 256, 0, sCSR>>>();
        scatter_k<<<(EE + 255) / 256, 256, 0, sCSR>>>(src, dst);
        cudaEventRecord(evCSR, sCSR);

        // stream B: weights + scores + projection 1
        prep_wb_k<<<(D1 * F_IN + 255) / 256, 256, 0, sB>>>(W1, W2);
        prep_wa_k<<<(3073 * 32 + 255) / 256, 256, 0, sB>>>(W1, a1, b1, ab1, W2, a2, b2, ab2);
        conv_score1_k<<<(MPAD + 7) / 8, 256, 0, sB>>>(h);
        maxss_k<1><<<64, 256, 0, sB>>>();
        {
            dim3 grid(MPAD / 64, D1 / 64);
            mma_k<1><<<grid, 256, 0, sB>>>(b1);
        }
        cudaEventRecord(evB, sB);

        // join: agg1 on default stream
        cudaStreamWaitEvent(0, evCSR, 0);
        cudaStreamWaitEvent(0, evB, 0);
        agg1_k<<<(NN + 7) / 8, 256>>>();

        // fork for layer 2: scores on sC, GEMM on default
        cudaEventRecord(ev1, 0);
        cudaStreamWaitEvent(sC, ev1, 0);
        score2_k<<<(NN + 7) / 8, 256, 0, sC>>>();
        maxss_k<2><<<64, 256, 0, sC>>>();
        cudaEventRecord(ev2, sC);
        {
            dim3 grid(MPAD / 64, D2 / 64);
            mma_k<2><<<grid, 256>>>(b2);
        }
        cudaStreamWaitEvent(0, ev2, 0);
        agg2_k<<<(NN + 7) / 8, 256>>>();

        reduce_k<<<(NN + 255) / 256, 256>>>();
        final_k<<<1, 32>>>(fc_w, fc_b, out);
    } else {
        // serial fallback
        zero_cnt_k<<<(NN + 255) / 256, 256>>>();
        prep_wb_k<<<(D1 * F_IN + 255) / 256, 256>>>(W1, W2);
        prep_wa_k<<<(3073 * 32 + 255) / 256, 256>>>(W1, a1, b1, ab1, W2, a2, b2, ab2);
        count_k<<<(EE + 255) / 256, 256>>>(dst);
        scan1_k<<<SBLKS, 256>>>();
        scan2_k<<<1, 256>>>();
        scan3_k<<<SBLKS, 256>>>();
        scatter_k<<<(EE + 255) / 256, 256>>>(src, dst);
        conv_score1_k<<<(MPAD + 7) / 8, 256>>>(h);
        maxss_k<1><<<64, 256>>>();
        {
            dim3 grid(MPAD / 64, D1 / 64);
            mma_k<1><<<grid, 256>>>(b1);
        }
        agg1_k<<<(NN + 7) / 8, 256>>>();
        {
            dim3 grid(MPAD / 64, D2 / 64);
            mma_k<2><<<grid, 256>>>(b2);
        }
        score2_k<<<(NN + 7) / 8, 256>>>();
        maxss_k<2><<<64, 256>>>();
        agg2_k<<<(NN + 7) / 8, 256>>>();
        reduce_k<<<(NN + 255) / 256, 256>>>();
        final_k<<<1, 32>>>(fc_w, fc_b, out);
    }
}